// round 9
// baseline (speedup 1.0000x reference)
#include <cuda_runtime.h>
#include <cuda_fp16.h>
#include <math.h>

#define NN 50000        // num nodes
#define DD 128          // embedding dim (= hidden dim)
#define BB 4            // num bases
#define EE 320000       // num edges
#define BH 512          // BB * DD

// ---------------- static scratch ----------------
__device__ float  g_x[NN * DD];          // node features, 25.6 MB
__device__ __half g_hb_h[NN * BH];       // per-base projections (fp16), 51.2 MB
__device__ int    g_deg[NN];
__device__ int    g_off[NN + 1];         // CSR row offsets (by dst)
__device__ int    g_cur[NN];             // fill cursors
__device__ int    g_elist[EE];           // edge ids bucketed by dst
__device__ double g_acc[3];              // loss_pos, loss_neg, auc_count

// ---------------- degree histogram ----------------
__global__ void k_zero_deg() {
    int i = blockIdx.x * blockDim.x + threadIdx.x;
    if (i < NN) g_deg[i] = 0;
}
__global__ void k_count_deg(const int* __restrict__ dst) {
    int e = blockIdx.x * blockDim.x + threadIdx.x;
    if (e < EE) atomicAdd(&g_deg[dst[e]], 1);
}

// ---------------- single-block prefix scan over degrees -> offsets ----------------
#define SCAN_T 1024
#define SCAN_CH 49          // ceil(50000 / 1024)
__global__ __launch_bounds__(SCAN_T) void k_scan() {
    __shared__ int sh[SCAN_T];
    int t = threadIdx.x;
    int base = t * SCAN_CH;
    int loc[SCAN_CH];
    int s = 0;
#pragma unroll
    for (int j = 0; j < SCAN_CH; j++) {
        int idx = base + j;
        loc[j] = s;
        if (idx < NN) s += g_deg[idx];
    }
    sh[t] = s;
    __syncthreads();
    // inclusive Hillis-Steele scan
    for (int off = 1; off < SCAN_T; off <<= 1) {
        int v = (t >= off) ? sh[t - off] : 0;
        __syncthreads();
        sh[t] += v;
        __syncthreads();
    }
    int pre = (t == 0) ? 0 : sh[t - 1];
#pragma unroll
    for (int j = 0; j < SCAN_CH; j++) {
        int idx = base + j;
        if (idx < NN) {
            int o = pre + loc[j];
            g_off[idx] = o;
            g_cur[idx] = o;
        }
    }
    if (t == SCAN_T - 1) g_off[NN] = sh[t];
}

// ---------------- bucket edges by dst ----------------
__global__ void k_fill(const int* __restrict__ dst) {
    int e = blockIdx.x * blockDim.x + threadIdx.x;
    if (e < EE) {
        int pos = atomicAdd(&g_cur[dst[e]], 1);
        g_elist[pos] = e;
    }
}

// ---------------- x0 = relu(emb + bias) (float4) ----------------
__global__ void k_x0(const float* __restrict__ emb, const float* __restrict__ eb) {
    int i = blockIdx.x * blockDim.x + threadIdx.x;     // float4 index
    if (i < NN * DD / 4) {
        float4 v = *(const float4*)&emb[i * 4];
        float4 bsv = *(const float4*)&eb[(i & 31) * 4];
        v.x = fmaxf(v.x + bsv.x, 0.f);
        v.y = fmaxf(v.y + bsv.y, 0.f);
        v.z = fmaxf(v.z + bsv.z, 0.f);
        v.w = fmaxf(v.w + bsv.w, 0.f);
        *(float4*)&g_x[i * 4] = v;
    }
}

// ---------------- tf32 helpers ----------------
__device__ __forceinline__ unsigned f2tf32(float f) {
    unsigned u;
    asm("cvt.rna.tf32.f32 %0, %1;" : "=r"(u) : "f"(f));
    return u;
}
__device__ __forceinline__ void mma_tf32(float c[4], const unsigned a[4], const unsigned b[2]) {
    asm volatile(
        "mma.sync.aligned.m16n8k8.row.col.f32.tf32.tf32.f32 "
        "{%0,%1,%2,%3}, {%4,%5,%6,%7}, {%8,%9}, {%0,%1,%2,%3};\n"
        : "+f"(c[0]), "+f"(c[1]), "+f"(c[2]), "+f"(c[3])
        : "r"(a[0]), "r"(a[1]), "r"(a[2]), "r"(a[3]), "r"(b[0]), "r"(b[1]));
}

// ---------------- tf32 GEMM: g_hb_h[N,512] = g_x[N,128] @ bases[b] (per-basis) ----------------
__global__ __launch_bounds__(256, 2) void k_gemm_mma(const float* __restrict__ bases) {
    __shared__ unsigned Xs[128][36];
    __shared__ unsigned Ws[32][136];

    const int b  = blockIdx.x;
    const int bm = blockIdx.y * 128;
    const int tid = threadIdx.x;
    const int lane = tid & 31;
    const int wid = tid >> 5;
    const int wm = wid & 3;
    const int wn = wid >> 2;
    const int gid = lane >> 2;
    const int tig = lane & 3;

    float c[2][8][4];
#pragma unroll
    for (int mt = 0; mt < 2; mt++)
#pragma unroll
        for (int nt = 0; nt < 8; nt++)
#pragma unroll
            for (int i = 0; i < 4; i++) c[mt][nt][i] = 0.f;

#pragma unroll
    for (int kc = 0; kc < 4; kc++) {
#pragma unroll
        for (int it = 0; it < 4; it++) {
            int idx = it * 256 + tid;
            int r = idx >> 3, c4 = idx & 7;
            float4 a = make_float4(0.f, 0.f, 0.f, 0.f);
            int grow = bm + r;
            if (grow < NN) a = *(const float4*)&g_x[grow * DD + kc * 32 + c4 * 4];
            uint4 u;
            u.x = f2tf32(a.x); u.y = f2tf32(a.y); u.z = f2tf32(a.z); u.w = f2tf32(a.w);
            *(uint4*)&Xs[r][c4 * 4] = u;
        }
#pragma unroll
        for (int it = 0; it < 4; it++) {
            int idx = it * 256 + tid;
            int r = idx >> 5, c4 = idx & 31;
            float4 a = *(const float4*)&bases[(b * DD + kc * 32 + r) * DD + c4 * 4];
            uint4 u;
            u.x = f2tf32(a.x); u.y = f2tf32(a.y); u.z = f2tf32(a.z); u.w = f2tf32(a.w);
            *(uint4*)&Ws[r][c4 * 4] = u;
        }
        __syncthreads();

#pragma unroll
        for (int ks = 0; ks < 4; ks++) {
            const int k0 = ks * 8 + tig;
            const int k1 = k0 + 4;
            unsigned a[2][4], bf[8][2];
#pragma unroll
            for (int mt = 0; mt < 2; mt++) {
                int mr = wm * 32 + mt * 16 + gid;
                a[mt][0] = Xs[mr][k0];
                a[mt][1] = Xs[mr + 8][k0];
                a[mt][2] = Xs[mr][k1];
                a[mt][3] = Xs[mr + 8][k1];
            }
#pragma unroll
            for (int nt = 0; nt < 8; nt++) {
                int nc = wn * 64 + nt * 8 + gid;
                bf[nt][0] = Ws[k0][nc];
                bf[nt][1] = Ws[k1][nc];
            }
#pragma unroll
            for (int mt = 0; mt < 2; mt++)
#pragma unroll
                for (int nt = 0; nt < 8; nt++)
                    mma_tf32(c[mt][nt], a[mt], bf[nt]);
        }
        __syncthreads();
    }

#pragma unroll
    for (int mt = 0; mt < 2; mt++) {
        int row0 = bm + wm * 32 + mt * 16 + gid;
        int row1 = row0 + 8;
#pragma unroll
        for (int nt = 0; nt < 8; nt++) {
            int col = b * 128 + wn * 64 + nt * 8 + 2 * tig;
            if (row0 < NN)
                *(__half2*)&g_hb_h[row0 * BH + col] = __floats2half2_rn(c[mt][nt][0], c[mt][nt][1]);
            if (row1 < NN)
                *(__half2*)&g_hb_h[row1 * BH + col] = __floats2half2_rn(c[mt][nt][2], c[mt][nt][3]);
        }
    }
}

// ---------------- pull-style aggregation: one warp per dst node, no atomics ----------------
// x[n] = [relu]( (sum_{e in bucket(n)} sum_b comp[et_e,b]*hb[src_e, b, :]) / max(deg,1) + bias )
__global__ __launch_bounds__(256) void k_agg(const int* __restrict__ src,
                                             const int* __restrict__ et,
                                             const float* __restrict__ comp,
                                             const float* __restrict__ bias,
                                             int do_relu) {
    int n = (blockIdx.x * blockDim.x + threadIdx.x) >> 5;
    int lane = threadIdx.x & 31;
    if (n >= NN) return;
    int beg = g_off[n], end = g_off[n + 1];
    float4 acc = make_float4(0.f, 0.f, 0.f, 0.f);
    for (int i = beg; i < end; i++) {
        int e = g_elist[i];
        int s = src[e], t = et[e];
        float c0 = __ldg(&comp[t * BB + 0]);
        float c1 = __ldg(&comp[t * BB + 1]);
        float c2 = __ldg(&comp[t * BB + 2]);
        float c3 = __ldg(&comp[t * BB + 3]);
        const uint2* hb = (const uint2*)&g_hb_h[(size_t)s * BH];
        uint2 u0 = hb[lane];            // base 0, dims lane*4..+3
        uint2 u1 = hb[32 + lane];       // base 1
        uint2 u2 = hb[64 + lane];       // base 2
        uint2 u3 = hb[96 + lane];       // base 3
        float2 a0 = __half22float2(*(const __half2*)&u0.x);
        float2 b0 = __half22float2(*(const __half2*)&u0.y);
        float2 a1 = __half22float2(*(const __half2*)&u1.x);
        float2 b1 = __half22float2(*(const __half2*)&u1.y);
        float2 a2 = __half22float2(*(const __half2*)&u2.x);
        float2 b2 = __half22float2(*(const __half2*)&u2.y);
        float2 a3 = __half22float2(*(const __half2*)&u3.x);
        float2 b3 = __half22float2(*(const __half2*)&u3.y);
        acc.x += c0 * a0.x + c1 * a1.x + c2 * a2.x + c3 * a3.x;
        acc.y += c0 * a0.y + c1 * a1.y + c2 * a2.y + c3 * a3.y;
        acc.z += c0 * b0.x + c1 * b1.x + c2 * b2.x + c3 * b3.x;
        acc.w += c0 * b0.y + c1 * b1.y + c2 * b2.y + c3 * b3.y;
    }
    float inv = 1.0f / fmaxf((float)(end - beg), 1.0f);
    float4 bsv = *(const float4*)&bias[lane * 4];
    acc.x = acc.x * inv + bsv.x;
    acc.y = acc.y * inv + bsv.y;
    acc.z = acc.z * inv + bsv.z;
    acc.w = acc.w * inv + bsv.w;
    if (do_relu) {
        acc.x = fmaxf(acc.x, 0.f); acc.y = fmaxf(acc.y, 0.f);
        acc.z = fmaxf(acc.z, 0.f); acc.w = fmaxf(acc.w, 0.f);
    }
    *(float4*)&g_x[n * DD + lane * 4] = acc;
}

// ---------------- decode ----------------
__global__ void k_zero_acc() {
    int i = threadIdx.x;
    if (i < 3) g_acc[i] = 0.0;
}

__device__ __forceinline__ float softplusf(float x) {
    return fmaxf(x, 0.f) + log1pf(expf(-fabsf(x)));
}

__global__ __launch_bounds__(256) void k_decode(const int* __restrict__ hh,
                                                const int* __restrict__ tt,
                                                const int* __restrict__ et,
                                                const int* __restrict__ ng,
                                                const float* __restrict__ rel,
                                                float* __restrict__ out) {
    __shared__ float s_lp[8], s_ln[8], s_au[8];
    int w = (blockIdx.x * blockDim.x + threadIdx.x) >> 5;
    int lane = threadIdx.x & 31;
    int wid = threadIdx.x >> 5;
    float lp = 0.f, ln = 0.f, au = 0.f;
    if (w < EE) {
        int a = hh[w], b = tt[w], c = ng[w], r = et[w];
        float4 xh = *(const float4*)&g_x[a * DD + lane * 4];
        float4 xt = *(const float4*)&g_x[b * DD + lane * 4];
        float4 xn = *(const float4*)&g_x[c * DD + lane * 4];
        float4 re = *(const float4*)&rel[r * DD + lane * 4];
        float hx = xh.x * re.x, hy = xh.y * re.y, hz = xh.z * re.z, hw = xh.w * re.w;
        float p = hx * xt.x + hy * xt.y + hz * xt.z + hw * xt.w;
        float q = hx * xn.x + hy * xn.y + hz * xn.z + hw * xn.w;
#pragma unroll
        for (int o = 16; o; o >>= 1) {
            p += __shfl_xor_sync(0xFFFFFFFFu, p, o);
            q += __shfl_xor_sync(0xFFFFFFFFu, q, o);
        }
        if (lane == 0) {
            out[w] = p;
            lp = softplusf(-p);
            ln = softplusf(q);
            au = (p > q) ? 1.f : 0.f;
        }
    }
    if (lane == 0) { s_lp[wid] = lp; s_ln[wid] = ln; s_au[wid] = au; }
    __syncthreads();
    if (threadIdx.x == 0) {
        double A = 0, Bd = 0, C = 0;
#pragma unroll
        for (int k = 0; k < 8; k++) { A += s_lp[k]; Bd += s_ln[k]; C += s_au[k]; }
        atomicAdd(&g_acc[0], A);
        atomicAdd(&g_acc[1], Bd);
        atomicAdd(&g_acc[2], C);
    }
}

__global__ void k_final(float* __restrict__ out, int out_size) {
    if (blockIdx.x == 0 && threadIdx.x == 0) {
        double inv = 1.0 / (double)EE;
        if (out_size >= EE + 1) out[EE] = (float)(0.5 * (g_acc[0] + g_acc[1]) * inv);
        if (out_size >= EE + 2) out[EE + 1] = (float)(g_acc[2] * inv);
    }
}

// ---------------- launch ----------------
extern "C" void kernel_launch(void* const* d_in, const int* in_sizes, int n_in,
                              void* d_out, int out_size) {
    const float* emb    = (const float*)d_in[0];
    const float* ebias  = (const float*)d_in[1];
    const float* bases1 = (const float*)d_in[2];
    const float* comp1  = (const float*)d_in[3];
    const float* bias1  = (const float*)d_in[4];
    const float* bases2 = (const float*)d_in[5];
    const float* comp2  = (const float*)d_in[6];
    const float* bias2  = (const float*)d_in[7];
    const float* rel    = (const float*)d_in[8];
    const int*   eidx   = (const int*)d_in[9];
    const int*   etype  = (const int*)d_in[10];
    const int*   negt   = (const int*)d_in[11];
    const int* src = eidx;
    const int* dst = eidx + EE;
    float* out = (float*)d_out;

    // CSR build (by dst) + x0 (independent of CSR)
    k_zero_deg<<<(NN + 255) / 256, 256>>>();
    k_count_deg<<<(EE + 255) / 256, 256>>>(dst);
    k_scan<<<1, SCAN_T>>>();
    k_fill<<<(EE + 255) / 256, 256>>>(dst);
    k_x0<<<(NN * DD / 4 + 255) / 256, 256>>>(emb, ebias);

    dim3 ggrid(BB, (NN + 127) / 128);   // (4, 391); blockIdx.x = basis
    int agg_blocks = (NN * 32 + 255) / 256;

    // ---- layer 1 ----
    k_gemm_mma<<<ggrid, 256>>>(bases1);
    k_agg<<<agg_blocks, 256>>>(src, etype, comp1, bias1, 1);

    // ---- layer 2 ----
    k_gemm_mma<<<ggrid, 256>>>(bases2);
    k_agg<<<agg_blocks, 256>>>(src, etype, comp2, bias2, 0);

    // ---- decode ----
    k_zero_acc<<<1, 32>>>();
    k_decode<<<EE / 8, 256>>>(src, dst, etype, negt, rel, out);
    k_final<<<1, 32>>>(out, out_size);
}